// round 1
// baseline (speedup 1.0000x reference)
#include <cuda_runtime.h>
#include <cstdint>

// Problem shape (fixed by the dataset's setup_inputs):
//   B=16, S=16384, T=4096, C=256, N0=16384
#define BB   16
#define SS   16384
#define TT   4096
#define CC   256
#define N0_LOG2 14   // N0 = 16384

// Per-target weight sums: B*T floats = 256 KB scratch (no allocation allowed).
__device__ float g_all_weight[BB * TT];

// ---------------------------------------------------------------------------
// Kernel 1: zero the output (poisoned by harness) and the weight table.
// ---------------------------------------------------------------------------
__global__ void zero_kernel(float4* __restrict__ out4, int n4) {
    const int stride = gridDim.x * blockDim.x;
    int i = blockIdx.x * blockDim.x + threadIdx.x;
    const float4 z = make_float4(0.f, 0.f, 0.f, 0.f);
    for (int j = i; j < n4; j += stride) out4[j] = z;
    if (i < BB * TT) g_all_weight[i] = 0.f;
}

// ---------------------------------------------------------------------------
// Kernel 2: all_weight[b,t] = sum of w over nonzeros targeting (b,t).
// One thread per nonzero. 262K atomics into 64K addresses, all L2-resident.
// ---------------------------------------------------------------------------
__global__ void weight_accum_kernel(const float* __restrict__ w,
                                    const int* __restrict__ idx_t,
                                    int BN) {
    int i = blockIdx.x * blockDim.x + threadIdx.x;
    if (i >= BN) return;
    int b = i >> N0_LOG2;
    atomicAdd(&g_all_weight[b * TT + idx_t[i]], w[i]);
}

// ---------------------------------------------------------------------------
// Kernel 3: weighted scatter. One warp per nonzero.
//   wn = w / (all_weight[b,t] + 1e-6)
//   out[b,t,:] += wn * x_s[b, s, :]    (C=256 -> 2 x float4 per lane)
// Vectorized no-return reduction (red.global.add.v4.f32) keeps the atomic
// lane count at 16.8M instead of 67M.
// ---------------------------------------------------------------------------
__global__ void __launch_bounds__(256)
scatter_kernel(const float4* __restrict__ xs4,
               const float* __restrict__ w,
               const int* __restrict__ idx_s,
               const int* __restrict__ idx_t,
               float* __restrict__ out,
               int BN) {
    int warp = (blockIdx.x * blockDim.x + threadIdx.x) >> 5;
    int lane = threadIdx.x & 31;
    if (warp >= BN) return;

    int b = warp >> N0_LOG2;
    int t = idx_t[warp];            // broadcast load (same addr per warp)
    int s = idx_s[warp];
    float sum = g_all_weight[b * TT + t];
    float wn  = w[warp] / (sum + 1e-6f);

    const float4* src = xs4 + (size_t)(b * SS + s) * (CC / 4);
    float*        dst = out + (size_t)(b * TT + t) * CC;

#pragma unroll
    for (int k = 0; k < 2; k++) {
        int c4 = lane + k * 32;             // float4 column index [0, 64)
        float4 v = __ldg(&src[c4]);
        float* d = dst + c4 * 4;            // 16B-aligned
        asm volatile("red.global.add.v4.f32 [%0], {%1, %2, %3, %4};"
                     :: "l"(d),
                        "f"(v.x * wn), "f"(v.y * wn),
                        "f"(v.z * wn), "f"(v.w * wn)
                     : "memory");
    }
}

// ---------------------------------------------------------------------------
// Launch
//   d_in[0] x_s        [B,S,C]  float32
//   d_in[1] agg_weight [B,N0,1] float32
//   d_in[2] idx_agg_s  [B,N0]   int32
//   d_in[3] idx_agg_t  [B,N0]   int32
//   d_in[4] T          scalar   (unused; T fixed at 4096)
//   d_out   x_out      [B,T,C]  float32
// ---------------------------------------------------------------------------
extern "C" void kernel_launch(void* const* d_in, const int* in_sizes, int n_in,
                              void* d_out, int out_size) {
    const float4* xs4  = (const float4*)d_in[0];
    const float*  w    = (const float*)d_in[1];
    const int*    is_  = (const int*)d_in[2];
    const int*    it_  = (const int*)d_in[3];
    float*        out  = (float*)d_out;

    const int BN = in_sizes[2];          // B * N0 = 262144
    const int n4 = out_size / 4;         // output float4 count

    // 1) zero output + weight table
    zero_kernel<<<4096, 256>>>((float4*)out, n4);

    // 2) per-target weight sums
    weight_accum_kernel<<<(BN + 255) / 256, 256>>>(w, it_, BN);

    // 3) normalized weighted scatter (1 warp / nonzero)
    scatter_kernel<<<(BN * 32 + 255) / 256, 256>>>(xs4, w, is_, it_, out, BN);
}

// round 3
// speedup vs baseline: 1.2594x; 1.2594x over previous
#include <cuda_runtime.h>
#include <cstdint>

// Problem shape (fixed by the dataset's setup_inputs):
//   B=16, S=16384, T=4096, C=256, N0=16384
#define BB      16
#define SS      16384
#define TT      4096
#define TT_LOG2 12
#define CC      256
#define N0_LOG2 14
#define BT      (BB * TT)        // 65536 output rows

#define MAXPER  32               // ELL slots per target row (mean fan-in = 4)
#define OVF_CAP 8192             // overflow fallback capacity

struct __align__(8) Entry { int s; float w; };

// Scratch (no runtime allocation allowed -> __device__ globals)
__device__ Entry g_entries[BT * MAXPER];     // 16 MB ELL buckets
__device__ int   g_count[BT];                // per-row fan-in
__device__ float g_allw[BT];                 // per-row weight sums
__device__ int   g_ovf_cnt;
__device__ int   g_ovf_seg[OVF_CAP];
__device__ int   g_ovf_s[OVF_CAP];
__device__ float g_ovf_w[OVF_CAP];

// ---------------------------------------------------------------------------
// Kernel 1: zero the small scratch (counts, weight sums, overflow counter).
// ---------------------------------------------------------------------------
__global__ void zero_scratch_kernel() {
    int i = blockIdx.x * blockDim.x + threadIdx.x;
    if (i < BT) { g_count[i] = 0; g_allw[i] = 0.f; }
    if (i == 0) g_ovf_cnt = 0;
}

// ---------------------------------------------------------------------------
// Kernel 2: bucket placement (ELL). One thread per nonzero.
//   - accumulate all_weight[seg] (covers overflow entries too)
//   - claim a slot via atomic cursor; overflow goes to the fallback list
// ---------------------------------------------------------------------------
__global__ void place_kernel(const float* __restrict__ w,
                             const int* __restrict__ idx_s,
                             const int* __restrict__ idx_t,
                             int BN) {
    int i = blockIdx.x * blockDim.x + threadIdx.x;
    if (i >= BN) return;
    int b   = i >> N0_LOG2;
    int seg = (b << TT_LOG2) + idx_t[i];
    float wv = w[i];
    atomicAdd(&g_allw[seg], wv);
    int pos = atomicAdd(&g_count[seg], 1);
    if (pos < MAXPER) {
        Entry e; e.s = idx_s[i]; e.w = wv;
        g_entries[seg * MAXPER + pos] = e;
    } else {
        int o = atomicAdd(&g_ovf_cnt, 1);
        if (o < OVF_CAP) {
            g_ovf_seg[o] = seg; g_ovf_s[o] = idx_s[i]; g_ovf_w[o] = wv;
        }
    }
}

// ---------------------------------------------------------------------------
// Kernel 3: gather. One warp per output row. No atomics, no output zero-init:
// every row (including empty ones) is written with plain vector stores.
//   out[row,:] = sum_e (w_e / (allw[row]+eps)) * x_s[b, s_e, :]
// C=256 -> 2 x float4 per lane. Entry loop unrolled x2 for MLP.
// ---------------------------------------------------------------------------
__global__ void __launch_bounds__(256)
gather_kernel(const float4* __restrict__ xs4, float4* __restrict__ out4) {
    int row  = (blockIdx.x * blockDim.x + threadIdx.x) >> 5;
    int lane = threadIdx.x & 31;
    if (row >= BT) return;

    int   cnt  = min(g_count[row], MAXPER);
    float invw = 1.0f / (g_allw[row] + 1e-6f);
    int   b    = row >> TT_LOG2;

    const Entry* e   = g_entries + (size_t)row * MAXPER;
    const float4* xb = xs4 + (size_t)b * SS * (CC / 4);

    float4 a0 = make_float4(0.f, 0.f, 0.f, 0.f);
    float4 a1 = make_float4(0.f, 0.f, 0.f, 0.f);

    int i = 0;
    for (; i + 2 <= cnt; i += 2) {
        Entry e0 = e[i], e1 = e[i + 1];
        const float4* s0 = xb + (size_t)e0.s * (CC / 4);
        const float4* s1 = xb + (size_t)e1.s * (CC / 4);
        float4 v00 = __ldg(&s0[lane]);
        float4 v01 = __ldg(&s0[lane + 32]);
        float4 v10 = __ldg(&s1[lane]);
        float4 v11 = __ldg(&s1[lane + 32]);
        float w0 = e0.w * invw, w1 = e1.w * invw;
        a0.x += w0 * v00.x; a0.y += w0 * v00.y; a0.z += w0 * v00.z; a0.w += w0 * v00.w;
        a1.x += w0 * v01.x; a1.y += w0 * v01.y; a1.z += w0 * v01.z; a1.w += w0 * v01.w;
        a0.x += w1 * v10.x; a0.y += w1 * v10.y; a0.z += w1 * v10.z; a0.w += w1 * v10.w;
        a1.x += w1 * v11.x; a1.y += w1 * v11.y; a1.z += w1 * v11.z; a1.w += w1 * v11.w;
    }
    if (i < cnt) {
        Entry e0 = e[i];
        const float4* s0 = xb + (size_t)e0.s * (CC / 4);
        float4 v00 = __ldg(&s0[lane]);
        float4 v01 = __ldg(&s0[lane + 32]);
        float w0 = e0.w * invw;
        a0.x += w0 * v00.x; a0.y += w0 * v00.y; a0.z += w0 * v00.z; a0.w += w0 * v00.w;
        a1.x += w0 * v01.x; a1.y += w0 * v01.y; a1.z += w0 * v01.z; a1.w += w0 * v01.w;
    }

    float4* dst = out4 + (size_t)row * (CC / 4);
    dst[lane]      = a0;
    dst[lane + 32] = a1;
}

// ---------------------------------------------------------------------------
// Kernel 4: overflow fixup (normally zero work). Atomically adds the rare
// entries that didn't fit their ELL bucket. Runs after gather (stream order),
// so the row base values are already in place.
// ---------------------------------------------------------------------------
__global__ void ovf_fixup_kernel(const float4* __restrict__ xs4,
                                 float* __restrict__ out) {
    int n = min(g_ovf_cnt, OVF_CAP);
    for (int o = blockIdx.x; o < n; o += gridDim.x) {
        int   seg  = g_ovf_seg[o];
        int   s    = g_ovf_s[o];
        float wn   = g_ovf_w[o] / (g_allw[seg] + 1e-6f);
        int   b    = seg >> TT_LOG2;
        const float* src = (const float*)(xs4 + ((size_t)b * SS + s) * (CC / 4));
        float* dst = out + (size_t)seg * CC;
        int c = threadIdx.x;           // 256 threads = 256 channels
        atomicAdd(&dst[c], wn * src[c]);
    }
}

// ---------------------------------------------------------------------------
// Launch
//   d_in[0] x_s        [B,S,C]  float32
//   d_in[1] agg_weight [B,N0,1] float32
//   d_in[2] idx_agg_s  [B,N0]   int32
//   d_in[3] idx_agg_t  [B,N0]   int32
//   d_in[4] T          scalar   (fixed 4096)
//   d_out   x_out      [B,T,C]  float32
// ---------------------------------------------------------------------------
extern "C" void kernel_launch(void* const* d_in, const int* in_sizes, int n_in,
                              void* d_out, int out_size) {
    const float4* xs4 = (const float4*)d_in[0];
    const float*  w   = (const float*)d_in[1];
    const int*    is_ = (const int*)d_in[2];
    const int*    it_ = (const int*)d_in[3];
    float*        out = (float*)d_out;

    const int BN = in_sizes[2];            // B * N0 = 262144

    // 1) zero the small scratch
    zero_scratch_kernel<<<(BT + 255) / 256, 256>>>();

    // 2) ELL bucket placement + per-row weight sums
    place_kernel<<<(BN + 255) / 256, 256>>>(w, is_, it_, BN);

    // 3) gather: warp per output row, plain stores (no output zeroing needed)
    gather_kernel<<<(BT * 32) / 256, 256>>>(xs4, (float4*)out);

    // 4) overflow fixup (normally a no-op)
    ovf_fixup_kernel<<<64, 256>>>(xs4, out);
}